// round 8
// baseline (speedup 1.0000x reference)
#include <cuda_runtime.h>
#include <cuda_fp16.h>
#include <math.h>
#include <cstdint>

#define Bb 64
#define Ll 12
#define Nn 4096
#define Cc 3
#define FDm 32
#define HDm 64
#define OUTD 12
#define TIDn 288
#define DIWn 7
#define TDm 16
#define NSTEPS 4
#define EMBm 10
#define BF (Bb*FDm)   // 2048

// Scratch (device globals)
__device__ float g_field[(size_t)Nn*BF];                    // field[n][b*32+f]
__device__ float g_state[(size_t)Nn*BF];
__device__ float g_AF[(size_t)Nn*BF];                       // A @ field (fp32)
__device__ __align__(16) __half g_Ah[(size_t)Nn*Nn];        // A fp16 [n][m]
__device__ __align__(16) __half g_FT[(size_t)BF*Nn];        // fieldT fp16 [j][m]

// ------------------------------ PTX helpers -------------------------------
__device__ __forceinline__ uint32_t smem_to_u32(const void* p) {
    uint32_t a;
    asm("{ .reg .u64 t; cvta.to.shared.u64 t, %1; cvt.u32.u64 %0, t; }"
        : "=r"(a) : "l"(p));
    return a;
}
__device__ __forceinline__ void cp16(uint32_t dst, const void* src) {
    asm volatile("cp.async.cg.shared.global [%0], [%1], 16;" :: "r"(dst), "l"(src));
}
#define CP_COMMIT() asm volatile("cp.async.commit_group;" ::: "memory")
#define CP_WAIT(n)  asm volatile("cp.async.wait_group %0;" :: "n"(n) : "memory")

__device__ __forceinline__ void ldsm4(uint32_t* r, uint32_t addr) {
    asm volatile("ldmatrix.sync.aligned.m8n8.x4.shared.b16 {%0,%1,%2,%3}, [%4];"
                 : "=r"(r[0]), "=r"(r[1]), "=r"(r[2]), "=r"(r[3]) : "r"(addr));
}
__device__ __forceinline__ void mma_f16(float* c, const uint32_t* a, const uint32_t* b) {
    asm volatile("mma.sync.aligned.m16n8k16.row.col.f32.f16.f16.f32 "
                 "{%0,%1,%2,%3}, {%4,%5,%6,%7}, {%8,%9}, {%0,%1,%2,%3};"
                 : "+f"(c[0]), "+f"(c[1]), "+f"(c[2]), "+f"(c[3])
                 : "r"(a[0]), "r"(a[1]), "r"(a[2]), "r"(a[3]), "r"(b[0]), "r"(b[1]));
}

// ---------------------------------------------------------------------------
// A = softmax(relu(node_emb @ node_emb^T)); register-resident row, fp16 out.
// ---------------------------------------------------------------------------
__global__ void __launch_bounds__(256) build_A(const float* __restrict__ emb) {
    int n = blockIdx.x;
    int tid = threadIdx.x;
    __shared__ float en[EMBm];
    __shared__ float red[256];
    if (tid < EMBm) en[tid] = emb[n*EMBm + tid];
    __syncthreads();

    float r[16];
    float lmax = 0.f;
    #pragma unroll
    for (int j = 0; j < 16; j++) {
        int m = j * 256 + tid;
        float d = 0.f;
        #pragma unroll
        for (int k = 0; k < EMBm; k++) d = fmaf(en[k], emb[m*EMBm + k], d);
        d = fmaxf(d, 0.f);
        r[j] = d;
        lmax = fmaxf(lmax, d);
    }
    red[tid] = lmax; __syncthreads();
    for (int s = 128; s > 0; s >>= 1) {
        if (tid < s) red[tid] = fmaxf(red[tid], red[tid+s]);
        __syncthreads();
    }
    float mx = red[0];
    __syncthreads();

    float lsum = 0.f;
    #pragma unroll
    for (int j = 0; j < 16; j++) {
        float e = expf(r[j] - mx);
        r[j] = e;
        lsum += e;
    }
    red[tid] = lsum; __syncthreads();
    for (int s = 128; s > 0; s >>= 1) {
        if (tid < s) red[tid] += red[tid+s];
        __syncthreads();
    }
    float inv = 1.f / red[0];

    #pragma unroll
    for (int j = 0; j < 16; j++) {
        int m = j * 256 + tid;
        g_Ah[(size_t)n*Nn + m] = __float2half_rn(r[j] * inv);
    }
}

// ---------------------------------------------------------------------------
// Transpose field to fp16: FT[j][m] = field[m][j]
// ---------------------------------------------------------------------------
__global__ void __launch_bounds__(256) split_field_T() {
    __shared__ float t[32][33];
    int j0 = blockIdx.x * 32;
    int n0 = blockIdx.y * 32;
    int tx = threadIdx.x & 31, ty = threadIdx.x >> 5;   // 32 x 8
    #pragma unroll
    for (int r = 0; r < 32; r += 8)
        t[ty + r][tx] = g_field[(size_t)(n0 + ty + r) * BF + j0 + tx];
    __syncthreads();
    #pragma unroll
    for (int r = 0; r < 32; r += 8) {
        float v = t[tx][ty + r];
        g_FT[(size_t)(j0 + ty + r) * Nn + n0 + tx] = __float2half_rn(v);
    }
}

// ---------------------------------------------------------------------------
// Encoder + temporal embedding. One warp per (b,n).
// ---------------------------------------------------------------------------
__global__ void __launch_bounds__(256) encoder_kernel(
    const float* __restrict__ hist,
    const float* __restrict__ tid_emb, const float* __restrict__ diw_emb,
    const float* __restrict__ t2f_w,   const float* __restrict__ t2f_b,
    const float* __restrict__ w1, const float* __restrict__ b1,
    const float* __restrict__ w2, const float* __restrict__ b2)
{
    __shared__ float s_w1[Ll*Cc*HDm];
    __shared__ float s_w2[HDm*FDm];
    __shared__ float s_t2f[2*TDm*FDm];
    __shared__ float s_b1[HDm];
    __shared__ float s_b2[FDm];
    __shared__ float s_t2fb[FDm];
    int tid = threadIdx.x;
    for (int i = tid; i < Ll*Cc*HDm; i += 256) s_w1[i] = w1[i];
    for (int i = tid; i < HDm*FDm;   i += 256) s_w2[i] = w2[i];
    for (int i = tid; i < 2*TDm*FDm; i += 256) s_t2f[i] = t2f_w[i];
    if (tid < HDm) s_b1[tid] = b1[tid];
    if (tid < FDm) { s_b2[tid] = b2[tid]; s_t2fb[tid] = t2f_b[tid]; }
    __syncthreads();

    int warp = (blockIdx.x * 256 + tid) >> 5;
    int lane = tid & 31;
    int n = warp & (Nn - 1);
    int b = warp >> 12;

    const float* hb = hist + ((size_t)b * Ll * Nn + n) * Cc;
    float x[Ll*Cc];
    #pragma unroll
    for (int l = 0; l < Ll; l++)
        #pragma unroll
        for (int c = 0; c < Cc; c++)
            x[l*Cc + c] = hb[(size_t)l * Nn * Cc + c];

    float h0 = s_b1[lane], h1 = s_b1[32 + lane];
    #pragma unroll
    for (int k = 0; k < Ll*Cc; k++) {
        h0 = fmaf(x[k], s_w1[k*HDm + lane],      h0);
        h1 = fmaf(x[k], s_w1[k*HDm + 32 + lane], h1);
    }
    h0 = fmaxf(h0, 0.f); h1 = fmaxf(h1, 0.f);

    float acc = s_b2[lane];
    #pragma unroll
    for (int hh = 0; hh < HDm; hh++) {
        float v = __shfl_sync(0xffffffffu, (hh < 32) ? h0 : h1, hh & 31);
        acc = fmaf(v, s_w2[hh*FDm + lane], acc);
    }

    float v1 = hb[(size_t)(Ll-1)*Nn*Cc + 1];
    float v2 = hb[(size_t)(Ll-1)*Nn*Cc + 2];
    int ti = (int)(v1 * (float)TIDn); ti = min(max(ti, 0), TIDn-1);
    int di = (int)(v2 * (float)DIWn); di = min(max(di, 0), DIWn-1);
    #pragma unroll
    for (int k = 0; k < TDm; k++)
        acc = fmaf(tid_emb[ti*TDm + k], s_t2f[k*FDm + lane], acc);
    #pragma unroll
    for (int k = 0; k < TDm; k++)
        acc = fmaf(diw_emb[di*TDm + k], s_t2f[(TDm + k)*FDm + lane], acc);
    acc += s_t2fb[lane];

    g_field[(size_t)n * BF + b*FDm + lane] = acc;
}

// ---------------------------------------------------------------------------
// fp16 tensor-core GEMM via mma.sync: g_AF = A @ field
// M=4096, N=2048, K=4096. CTA 128x128xBK32, 8 warps (2x4), warp tile 64x32.
// Single-pass fp16 A. 4-stage cp.async pipeline, 2 CTAs/SM.
// ---------------------------------------------------------------------------
#define BKg 32
#define LDAe 40                       // padded row stride (halfs) = 80 B
#define TILE_BYTES (128*LDAe*2)       // 10240
#define STG_BYTES (2*TILE_BYTES)      // 20480 (A, B)
#define NST 4
#define GSMEM (NST*STG_BYTES)         // 81920

__global__ void __launch_bounds__(256, 2) gemm_mma()
{
    extern __shared__ char smem[];
    uint32_t sbase = smem_to_u32(smem);
    int tid = threadIdx.x;
    int lane = tid & 31;
    int wid = tid >> 5;
    int bcol = blockIdx.x;    // 0..15
    int brow = blockIdx.y;    // 0..31

    const __half* Ah = g_Ah + (size_t)brow * 128 * Nn;
    const __half* Bt = g_FT + (size_t)bcol * 128 * Nn;

    // loader: thread t covers row t/2, 16-half chunk (t&1)
    int lr = tid >> 1;
    int lc = (tid & 1) * 16;
    size_t goff = (size_t)lr * Nn + lc;
    uint32_t sdst = sbase + lr * (LDAe*2) + lc * 2;

    int warp_m = wid & 1;
    int warp_n = wid >> 1;
    int m_base = warp_m * 64;
    int n_base = warp_n * 32;

    float acc[4][4][4];
    #pragma unroll
    for (int i = 0; i < 4; i++)
        #pragma unroll
        for (int j = 0; j < 4; j++)
            #pragma unroll
            for (int q = 0; q < 4; q++) acc[i][j][q] = 0.f;

    uint32_t a_off[4];
    #pragma unroll
    for (int i = 0; i < 4; i++)
        a_off[i] = (m_base + i*16 + (lane & 15)) * (LDAe*2) + ((lane >> 4) * 8) * 2;
    uint32_t b_off[2];
    #pragma unroll
    for (int j = 0; j < 2; j++)
        b_off[j] = (n_base + j*16 + ((lane >> 4) << 3) + (lane & 7)) * (LDAe*2)
                 + (((lane >> 3) & 1) * 8) * 2;

    const int NIT = Nn / BKg;   // 128

    // prefetch stages 0..2
    #pragma unroll
    for (int p = 0; p < 3; p++) {
        uint32_t d = p * STG_BYTES;
        size_t g = goff + (size_t)p * BKg;
        cp16(sdst + d,              Ah + g); cp16(sdst + d + 16,              Ah + g + 8);
        cp16(sdst + d + TILE_BYTES, Bt + g); cp16(sdst + d + TILE_BYTES + 16, Bt + g + 8);
        CP_COMMIT();
    }

    for (int it = 0; it < NIT; it++) {
        CP_WAIT(2);
        __syncthreads();

        if (it + 3 < NIT) {
            uint32_t d = ((it + 3) & 3) * STG_BYTES;
            size_t g = goff + (size_t)(it + 3) * BKg;
            cp16(sdst + d,              Ah + g); cp16(sdst + d + 16,              Ah + g + 8);
            cp16(sdst + d + TILE_BYTES, Bt + g); cp16(sdst + d + TILE_BYTES + 16, Bt + g + 8);
        }
        CP_COMMIT();   // commit (possibly empty) to keep group ledger aligned

        uint32_t st = sbase + (it & 3) * STG_BYTES;
        #pragma unroll
        for (int kk = 0; kk < 2; kk++) {
            uint32_t koff = kk * 16 * 2;
            uint32_t af[4][4];
            #pragma unroll
            for (int i = 0; i < 4; i++)
                ldsm4(af[i], st + a_off[i] + koff);
            uint32_t bf[2][4];
            #pragma unroll
            for (int j = 0; j < 2; j++)
                ldsm4(bf[j], st + TILE_BYTES + b_off[j] + koff);
            #pragma unroll
            for (int i = 0; i < 4; i++)
                #pragma unroll
                for (int na = 0; na < 4; na++)
                    mma_f16(acc[i][na], af[i], &bf[na >> 1][(na & 1) * 2]);
        }
    }

    __syncthreads();

    int grow0 = brow * 128 + m_base + (lane >> 2);
    int gcol0 = bcol * 128 + n_base + 2 * (lane & 3);
    #pragma unroll
    for (int i = 0; i < 4; i++) {
        #pragma unroll
        for (int na = 0; na < 4; na++) {
            float* p0 = g_AF + (size_t)(grow0 + i*16)     * BF + gcol0 + na*8;
            float* p1 = g_AF + (size_t)(grow0 + i*16 + 8) * BF + gcol0 + na*8;
            *(float2*)p0 = make_float2(acc[i][na][0], acc[i][na][1]);
            *(float2*)p1 = make_float2(acc[i][na][2], acc[i][na][3]);
        }
    }
}

// ---------------------------------------------------------------------------
// Per-step pointwise + small MLPs. Thread-per-point.
// ---------------------------------------------------------------------------
__global__ void __launch_bounds__(256) step_kernel(
    const float* __restrict__ pw1, const float* __restrict__ pb1,
    const float* __restrict__ pw2, const float* __restrict__ pb2,
    const float* __restrict__ win, const float* __restrict__ wst,
    const float* __restrict__ sb,  const float* __restrict__ wout,
    const float* __restrict__ bout, const float* __restrict__ pde_mix,
    int first)
{
    __shared__ float s_w1[FDm*HDm], s_w2[HDm*FDm];
    __shared__ float s_win[FDm*FDm], s_wst[FDm*FDm], s_wout[FDm*FDm];
    __shared__ float s_b1[HDm], s_b2[FDm], s_sb[FDm], s_bout[FDm];
    int tid = threadIdx.x;
    for (int i = tid; i < FDm*HDm; i += 256) { s_w1[i] = pw1[i]; s_w2[i] = pw2[i]; }
    for (int i = tid; i < FDm*FDm; i += 256) { s_win[i] = win[i]; s_wst[i] = wst[i]; s_wout[i] = wout[i]; }
    if (tid < HDm) s_b1[tid] = pb1[tid];
    if (tid < FDm) { s_b2[tid] = pb2[tid]; s_sb[tid] = sb[tid]; s_bout[tid] = bout[tid]; }
    __syncthreads();

    float alpha = 1.f / (1.f + expf(-pde_mix[0]));
    const float dtc = 1.f / NSTEPS;

    size_t p = (size_t)blockIdx.x * 256 + tid;
    float* fbase = g_field + p * FDm;
    const float* abase = g_AF + p * FDm;
    float* sbase_g = g_state + p * FDm;

    float x[FDm];
    #pragma unroll
    for (int i = 0; i < FDm/4; i++) *(float4*)&x[i*4] = *(const float4*)(fbase + i*4);

    float h[HDm];
    #pragma unroll
    for (int hh = 0; hh < HDm; hh++) h[hh] = s_b1[hh];
    #pragma unroll
    for (int k = 0; k < FDm; k++) {
        float xk = x[k];
        #pragma unroll
        for (int hh = 0; hh < HDm; hh++)
            h[hh] = fmaf(xk, s_w1[k*HDm + hh], h[hh]);
    }
    #pragma unroll
    for (int hh = 0; hh < HDm; hh++) h[hh] = fmaxf(h[hh], 0.f);

    float nf[FDm];
    #pragma unroll
    for (int f = 0; f < FDm; f++) nf[f] = s_b2[f];
    #pragma unroll
    for (int hh = 0; hh < HDm; hh++) {
        float hv = h[hh];
        #pragma unroll
        for (int f = 0; f < FDm; f++)
            nf[f] = fmaf(hv, s_w2[hh*FDm + f], nf[f]);
    }

    float fe[FDm];
    #pragma unroll
    for (int i = 0; i < FDm/4; i++) {
        float4 af4 = *(const float4*)(abase + i*4);
        float afv[4] = {af4.x, af4.y, af4.z, af4.w};
        #pragma unroll
        for (int q = 0; q < 4; q++) {
            int f = i*4 + q;
            fe[f] = x[f] + (alpha*(afv[q] - x[f]) + (1.f - alpha)*nf[f]) * dtc;
        }
    }

    float st[FDm];
    if (first) {
        #pragma unroll
        for (int f = 0; f < FDm; f++) st[f] = 0.f;
    } else {
        #pragma unroll
        for (int i = 0; i < FDm/4; i++) *(float4*)&st[i*4] = *(const float4*)(sbase_g + i*4);
    }

    float sa[FDm];
    #pragma unroll
    for (int f = 0; f < FDm; f++) sa[f] = s_sb[f];
    #pragma unroll
    for (int k = 0; k < FDm; k++) {
        float fk = fe[k], sk = st[k];
        #pragma unroll
        for (int f = 0; f < FDm; f++) {
            sa[f] = fmaf(fk, s_win[k*FDm + f], sa[f]);
            sa[f] = fmaf(sk, s_wst[k*FDm + f], sa[f]);
        }
    }
    float stn[FDm];
    #pragma unroll
    for (int f = 0; f < FDm; f++) stn[f] = tanhf(sa[f]);
    #pragma unroll
    for (int i = 0; i < FDm/4; i++) *(float4*)(sbase_g + i*4) = *(float4*)&stn[i*4];

    float fout[FDm];
    #pragma unroll
    for (int f = 0; f < FDm; f++) fout[f] = fe[f] + s_bout[f];
    #pragma unroll
    for (int k = 0; k < FDm; k++) {
        float sk = stn[k];
        #pragma unroll
        for (int f = 0; f < FDm; f++)
            fout[f] = fmaf(sk, s_wout[k*FDm + f], fout[f]);
    }
    #pragma unroll
    for (int i = 0; i < FDm/4; i++) *(float4*)(fbase + i*4) = *(float4*)&fout[i*4];
}

// ---------------------------------------------------------------------------
// Decoder. One warp per (b,n). out[(b*12+o)*4096 + n]
// ---------------------------------------------------------------------------
__global__ void __launch_bounds__(256) decoder_kernel(
    const float* __restrict__ w1, const float* __restrict__ b1,
    const float* __restrict__ w2, const float* __restrict__ b2,
    float* __restrict__ out)
{
    __shared__ float s_w1[FDm*HDm], s_w2[HDm*OUTD];
    __shared__ float s_b1[HDm], s_b2[OUTD];
    int tid = threadIdx.x;
    for (int i = tid; i < FDm*HDm;  i += 256) s_w1[i] = w1[i];
    for (int i = tid; i < HDm*OUTD; i += 256) s_w2[i] = w2[i];
    if (tid < HDm) s_b1[tid] = b1[tid];
    if (tid < OUTD) s_b2[tid] = b2[tid];
    __syncthreads();

    int warp = (blockIdx.x * 256 + tid) >> 5;
    int lane = tid & 31;
    int b = warp & 63;
    int n = warp >> 6;

    float fld = g_field[(size_t)n * BF + b*FDm + lane];
    float h0 = s_b1[lane], h1 = s_b1[32 + lane];
    #pragma unroll
    for (int k = 0; k < FDm; k++) {
        float fk = __shfl_sync(0xffffffffu, fld, k);
        h0 = fmaf(fk, s_w1[k*HDm + lane],      h0);
        h1 = fmaf(fk, s_w1[k*HDm + 32 + lane], h1);
    }
    h0 = fmaxf(h0, 0.f); h1 = fmaxf(h1, 0.f);

    float o = (lane < OUTD) ? s_b2[lane] : 0.f;
    #pragma unroll
    for (int hh = 0; hh < HDm; hh++) {
        float v = __shfl_sync(0xffffffffu, (hh < 32) ? h0 : h1, hh & 31);
        if (lane < OUTD) o = fmaf(v, s_w2[hh*OUTD + lane], o);
    }
    if (lane < OUTD)
        out[((size_t)b*OUTD + lane)*Nn + n] = o;
}

// ---------------------------------------------------------------------------
extern "C" void kernel_launch(void* const* d_in, const int* in_sizes, int n_in,
                              void* d_out, int out_size)
{
    const float* hist     = (const float*)d_in[0];
    const float* tid_emb  = (const float*)d_in[5];
    const float* diw_emb  = (const float*)d_in[6];
    const float* t2f_w    = (const float*)d_in[7];
    const float* t2f_b    = (const float*)d_in[8];
    const float* enc_w1   = (const float*)d_in[9];
    const float* enc_b1   = (const float*)d_in[10];
    const float* enc_w2   = (const float*)d_in[11];
    const float* enc_b2   = (const float*)d_in[12];
    const float* node_emb = (const float*)d_in[13];
    const float* pde_w1   = (const float*)d_in[14];
    const float* pde_b1   = (const float*)d_in[15];
    const float* pde_w2   = (const float*)d_in[16];
    const float* pde_b2   = (const float*)d_in[17];
    const float* ss_win   = (const float*)d_in[18];
    const float* ss_wst   = (const float*)d_in[19];
    const float* ss_b     = (const float*)d_in[20];
    const float* ss_wout  = (const float*)d_in[21];
    const float* ss_bout  = (const float*)d_in[22];
    const float* dec_w1   = (const float*)d_in[23];
    const float* dec_b1   = (const float*)d_in[24];
    const float* dec_w2   = (const float*)d_in[25];
    const float* dec_b2   = (const float*)d_in[26];
    const float* pde_mix  = (const float*)d_in[27];

    static int smem_set = 0;
    if (!smem_set) {
        cudaFuncSetAttribute(gemm_mma, cudaFuncAttributeMaxDynamicSharedMemorySize, GSMEM);
        smem_set = 1;
    }

    build_A<<<Nn, 256>>>(node_emb);

    encoder_kernel<<<(Bb*Nn)/8, 256>>>(hist, tid_emb, diw_emb, t2f_w, t2f_b,
                                       enc_w1, enc_b1, enc_w2, enc_b2);

    for (int s = 0; s < NSTEPS; s++) {
        split_field_T<<<dim3(BF/32, Nn/32), 256>>>();
        gemm_mma<<<dim3(BF/128, Nn/128), 256, GSMEM>>>();
        step_kernel<<<(Bb*Nn)/256, 256>>>(pde_w1, pde_b1, pde_w2, pde_b2,
                                          ss_win, ss_wst, ss_b, ss_wout, ss_bout,
                                          pde_mix, s == 0);
    }

    decoder_kernel<<<(Bb*Nn)/8, 256>>>(dec_w1, dec_b1, dec_w2, dec_b2,
                                       (float*)d_out);
}

// round 10
// speedup vs baseline: 1.7142x; 1.7142x over previous
#include <cuda_runtime.h>
#include <cuda_fp16.h>
#include <math.h>
#include <cstdint>

#define Bb 64
#define Ll 12
#define Nn 4096
#define Cc 3
#define FDm 32
#define HDm 64
#define OUTD 12
#define TIDn 288
#define DIWn 7
#define TDm 16
#define NSTEPS 4
#define EMBm 10
#define BF (Bb*FDm)   // 2048

// Scratch (device globals)
__device__ float g_field[(size_t)Nn*BF];                    // field[m][j], j=b*32+f
__device__ float g_state[(size_t)Nn*BF];
__device__ __align__(16) __half g_Ah[(size_t)Nn*Nn];        // A fp16 [n][m]
__device__ __align__(16) __half g_Fh[2][(size_t)Nn*BF];     // field fp16 [m][j], dbl-buf

// ------------------------------ PTX helpers -------------------------------
__device__ __forceinline__ uint32_t smem_to_u32(const void* p) {
    uint32_t a;
    asm("{ .reg .u64 t; cvta.to.shared.u64 t, %1; cvt.u32.u64 %0, t; }"
        : "=r"(a) : "l"(p));
    return a;
}
__device__ __forceinline__ void cp16(uint32_t dst, const void* src) {
    asm volatile("cp.async.cg.shared.global [%0], [%1], 16;" :: "r"(dst), "l"(src));
}
#define CP_COMMIT() asm volatile("cp.async.commit_group;" ::: "memory")
#define CP_WAIT(n)  asm volatile("cp.async.wait_group %0;" :: "n"(n) : "memory")

__device__ __forceinline__ void ldsm4(uint32_t* r, uint32_t addr) {
    asm volatile("ldmatrix.sync.aligned.m8n8.x4.shared.b16 {%0,%1,%2,%3}, [%4];"
                 : "=r"(r[0]), "=r"(r[1]), "=r"(r[2]), "=r"(r[3]) : "r"(addr));
}
__device__ __forceinline__ void ldsm4t(uint32_t* r, uint32_t addr) {
    asm volatile("ldmatrix.sync.aligned.m8n8.x4.trans.shared.b16 {%0,%1,%2,%3}, [%4];"
                 : "=r"(r[0]), "=r"(r[1]), "=r"(r[2]), "=r"(r[3]) : "r"(addr));
}
__device__ __forceinline__ void mma_f16(float* c, const uint32_t* a, const uint32_t* b) {
    asm volatile("mma.sync.aligned.m16n8k16.row.col.f32.f16.f16.f32 "
                 "{%0,%1,%2,%3}, {%4,%5,%6,%7}, {%8,%9}, {%0,%1,%2,%3};"
                 : "+f"(c[0]), "+f"(c[1]), "+f"(c[2]), "+f"(c[3])
                 : "r"(a[0]), "r"(a[1]), "r"(a[2]), "r"(a[3]), "r"(b[0]), "r"(b[1]));
}

// ---------------------------------------------------------------------------
// A = softmax(relu(node_emb @ node_emb^T)); register-resident row, fp16 out.
// ---------------------------------------------------------------------------
__global__ void __launch_bounds__(256) build_A(const float* __restrict__ emb) {
    int n = blockIdx.x;
    int tid = threadIdx.x;
    __shared__ float en[EMBm];
    __shared__ float red[256];
    if (tid < EMBm) en[tid] = emb[n*EMBm + tid];
    __syncthreads();

    float r[16];
    float lmax = 0.f;
    #pragma unroll
    for (int j = 0; j < 16; j++) {
        int m = j * 256 + tid;
        float d = 0.f;
        #pragma unroll
        for (int k = 0; k < EMBm; k++) d = fmaf(en[k], emb[m*EMBm + k], d);
        d = fmaxf(d, 0.f);
        r[j] = d;
        lmax = fmaxf(lmax, d);
    }
    red[tid] = lmax; __syncthreads();
    for (int s = 128; s > 0; s >>= 1) {
        if (tid < s) red[tid] = fmaxf(red[tid], red[tid+s]);
        __syncthreads();
    }
    float mx = red[0];
    __syncthreads();

    float lsum = 0.f;
    #pragma unroll
    for (int j = 0; j < 16; j++) {
        float e = expf(r[j] - mx);
        r[j] = e;
        lsum += e;
    }
    red[tid] = lsum; __syncthreads();
    for (int s = 128; s > 0; s >>= 1) {
        if (tid < s) red[tid] += red[tid+s];
        __syncthreads();
    }
    float inv = 1.f / red[0];

    #pragma unroll
    for (int j = 0; j < 16; j++) {
        int m = j * 256 + tid;
        g_Ah[(size_t)n*Nn + m] = __float2half_rn(r[j] * inv);
    }
}

// ---------------------------------------------------------------------------
// Encoder + temporal embedding. One warp per (b,n). Writes fp32 + fp16 field.
// ---------------------------------------------------------------------------
__global__ void __launch_bounds__(256) encoder_kernel(
    const float* __restrict__ hist,
    const float* __restrict__ tid_emb, const float* __restrict__ diw_emb,
    const float* __restrict__ t2f_w,   const float* __restrict__ t2f_b,
    const float* __restrict__ w1, const float* __restrict__ b1,
    const float* __restrict__ w2, const float* __restrict__ b2)
{
    __shared__ float s_w1[Ll*Cc*HDm];
    __shared__ float s_w2[HDm*FDm];
    __shared__ float s_t2f[2*TDm*FDm];
    __shared__ float s_b1[HDm];
    __shared__ float s_b2[FDm];
    __shared__ float s_t2fb[FDm];
    int tid = threadIdx.x;
    for (int i = tid; i < Ll*Cc*HDm; i += 256) s_w1[i] = w1[i];
    for (int i = tid; i < HDm*FDm;   i += 256) s_w2[i] = w2[i];
    for (int i = tid; i < 2*TDm*FDm; i += 256) s_t2f[i] = t2f_w[i];
    if (tid < HDm) s_b1[tid] = b1[tid];
    if (tid < FDm) { s_b2[tid] = b2[tid]; s_t2fb[tid] = t2f_b[tid]; }
    __syncthreads();

    int warp = (blockIdx.x * 256 + tid) >> 5;
    int lane = tid & 31;
    int n = warp & (Nn - 1);
    int b = warp >> 12;

    const float* hb = hist + ((size_t)b * Ll * Nn + n) * Cc;
    float x[Ll*Cc];
    #pragma unroll
    for (int l = 0; l < Ll; l++)
        #pragma unroll
        for (int c = 0; c < Cc; c++)
            x[l*Cc + c] = hb[(size_t)l * Nn * Cc + c];

    float h0 = s_b1[lane], h1 = s_b1[32 + lane];
    #pragma unroll
    for (int k = 0; k < Ll*Cc; k++) {
        h0 = fmaf(x[k], s_w1[k*HDm + lane],      h0);
        h1 = fmaf(x[k], s_w1[k*HDm + 32 + lane], h1);
    }
    h0 = fmaxf(h0, 0.f); h1 = fmaxf(h1, 0.f);

    float acc = s_b2[lane];
    #pragma unroll
    for (int hh = 0; hh < HDm; hh++) {
        float v = __shfl_sync(0xffffffffu, (hh < 32) ? h0 : h1, hh & 31);
        acc = fmaf(v, s_w2[hh*FDm + lane], acc);
    }

    float v1 = hb[(size_t)(Ll-1)*Nn*Cc + 1];
    float v2 = hb[(size_t)(Ll-1)*Nn*Cc + 2];
    int ti = (int)(v1 * (float)TIDn); ti = min(max(ti, 0), TIDn-1);
    int di = (int)(v2 * (float)DIWn); di = min(max(di, 0), DIWn-1);
    #pragma unroll
    for (int k = 0; k < TDm; k++)
        acc = fmaf(tid_emb[ti*TDm + k], s_t2f[k*FDm + lane], acc);
    #pragma unroll
    for (int k = 0; k < TDm; k++)
        acc = fmaf(diw_emb[di*TDm + k], s_t2f[(TDm + k)*FDm + lane], acc);
    acc += s_t2fb[lane];

    size_t off = (size_t)n * BF + b*FDm + lane;
    g_field[off] = acc;
    g_Fh[0][off] = __float2half_rn(acc);
}

// ---------------------------------------------------------------------------
// FUSED: fp16 tensor-core GEMM (AF = A @ field) + per-point step MLP epilogue.
// CTA 128x128xBK32, 8 warps (2x4), warp tile 64x32, 4-stage cp.async, 2 CTA/SM.
// B operand point-major [m][j] via ldmatrix.trans. Epilogue updates field/state
// and writes next-step fp16 B into the other g_Fh buffer.
// ---------------------------------------------------------------------------
#define BKg 32
#define LDAe 40                        // A tile pitch (halfs) = 80 B
#define TA_BYTES (128*LDAe*2)          // 10240
#define LDBB 136                       // B tile pitch (halfs) = 272 B
#define TB_BYTES (BKg*LDBB*2)          // 8704
#define STG_BYTES (TA_BYTES + TB_BYTES)  // 18944
#define NST 4
#define PIPE_BYTES (NST*STG_BYTES)     // 75776
#define CSM_PITCH 132
#define CSM_BYTES (128*CSM_PITCH*4)    // 67584
#define GSMEM (CSM_BYTES + (2048+2048+3*1024+160)*4)  // 96896

__global__ void __launch_bounds__(256, 2) gemm_fused(
    const float* __restrict__ pw1, const float* __restrict__ pb1,
    const float* __restrict__ pw2, const float* __restrict__ pb2,
    const float* __restrict__ win, const float* __restrict__ wst,
    const float* __restrict__ sb,  const float* __restrict__ wout,
    const float* __restrict__ bout, const float* __restrict__ pde_mix,
    int first, int rbuf)
{
    extern __shared__ char smem[];
    uint32_t sbase = smem_to_u32(smem);
    int tid = threadIdx.x;
    int lane = tid & 31;
    int wid = tid >> 5;
    int bcol = blockIdx.x;    // 0..15
    int brow = blockIdx.y;    // 0..31

    const __half* Ah = g_Ah + (size_t)brow * 128 * Nn;
    const __half* Bg = g_Fh[rbuf] + (size_t)bcol * 128;   // [m][j0 + ...]

    // A loader: thread t -> row t/2 (0..127), 16-half chunk (t&1)
    int alr = tid >> 1;
    int alc = (tid & 1) * 16;
    size_t gA = (size_t)alr * Nn + alc;
    uint32_t sA = sbase + alr * (LDAe*2) + alc * 2;
    // B loader: thread t -> k-row t/8 (0..31), 16-half chunk (t&7)
    int blr = tid >> 3;
    int blc = (tid & 7) * 16;
    uint32_t sB = sbase + TA_BYTES + blr * (LDBB*2) + blc * 2;

    int warp_m = wid & 1;
    int warp_n = wid >> 1;
    int m_base = warp_m * 64;
    int n_base = warp_n * 32;

    float acc[4][4][4];
    #pragma unroll
    for (int i = 0; i < 4; i++)
        #pragma unroll
        for (int j = 0; j < 4; j++)
            #pragma unroll
            for (int q = 0; q < 4; q++) acc[i][j][q] = 0.f;

    uint32_t a_off[4];
    #pragma unroll
    for (int i = 0; i < 4; i++)
        a_off[i] = (m_base + i*16 + (lane & 15)) * (LDAe*2) + ((lane >> 4) * 8) * 2;
    // B (trans): lane l -> matrix i=l>>3; k-row = (i&1)*8 + (l&7); n-col = nj*16 + (i>>1)*8
    uint32_t b_off[2];
    {
        int i = lane >> 3;
        #pragma unroll
        for (int nj = 0; nj < 2; nj++)
            b_off[nj] = ((i & 1) * 8 + (lane & 7)) * (LDBB*2)
                      + (n_base + nj*16 + (i >> 1) * 8) * 2;
    }

    const int NIT = Nn / BKg;   // 128

    // prefetch stages 0..2
    #pragma unroll
    for (int p = 0; p < 3; p++) {
        uint32_t d = p * STG_BYTES;
        size_t kg = (size_t)p * BKg;
        cp16(sA + d,      Ah + gA + kg); cp16(sA + d + 16, Ah + gA + kg + 8);
        const __half* bs = Bg + (kg + blr) * BF + blc;
        cp16(sB + d,      bs);           cp16(sB + d + 16, bs + 8);
        CP_COMMIT();
    }

    for (int it = 0; it < NIT; it++) {
        CP_WAIT(2);
        __syncthreads();

        if (it + 3 < NIT) {
            uint32_t d = ((it + 3) & 3) * STG_BYTES;
            size_t kg = (size_t)(it + 3) * BKg;
            cp16(sA + d,      Ah + gA + kg); cp16(sA + d + 16, Ah + gA + kg + 8);
            const __half* bs = Bg + (kg + blr) * BF + blc;
            cp16(sB + d,      bs);           cp16(sB + d + 16, bs + 8);
        }
        CP_COMMIT();

        uint32_t st = sbase + (it & 3) * STG_BYTES;
        #pragma unroll
        for (int kk = 0; kk < 2; kk++) {
            uint32_t af[4][4];
            #pragma unroll
            for (int i = 0; i < 4; i++)
                ldsm4(af[i], st + a_off[i] + kk * 32);
            uint32_t bf[2][4];
            #pragma unroll
            for (int j = 0; j < 2; j++)
                ldsm4t(bf[j], st + TA_BYTES + b_off[j] + kk * 16 * (LDBB*2));
            #pragma unroll
            for (int i = 0; i < 4; i++)
                #pragma unroll
                for (int na = 0; na < 4; na++)
                    mma_f16(acc[i][na], af[i], &bf[na >> 1][(na & 1) * 2]);
        }
    }
    CP_WAIT(0);
    __syncthreads();   // all tile reads done; smem is now repurposed

    // ---------------- epilogue: step MLP on 512 points -----------------
    float* Csm  = (float*)smem;                 // [128][132]
    float* sw1  = (float*)(smem + CSM_BYTES);   // 32x64
    float* sw2  = sw1 + 2048;                   // 64x32
    float* swin = sw2 + 2048;
    float* swst = swin + 1024;
    float* swou = swst + 1024;
    float* sbia = swou + 1024;                  // b1[64], b2[32], sb[32], bout[32]

    for (int i = tid; i < 2048; i += 256) { sw1[i] = pw1[i]; sw2[i] = pw2[i]; }
    for (int i = tid; i < 1024; i += 256) { swin[i] = win[i]; swst[i] = wst[i]; swou[i] = wout[i]; }
    if (tid < 64) sbia[tid] = pb1[tid];
    if (tid < 32) { sbia[64+tid] = pb2[tid]; sbia[96+tid] = sb[tid]; sbia[128+tid] = bout[tid]; }

    // dump accumulators to Csm
    #pragma unroll
    for (int i = 0; i < 4; i++) {
        int r = m_base + i*16 + (lane >> 2);
        #pragma unroll
        for (int na = 0; na < 4; na++) {
            int c = n_base + na*8 + 2*(lane & 3);
            Csm[r*CSM_PITCH + c]       = acc[i][na][0];
            Csm[r*CSM_PITCH + c + 1]   = acc[i][na][1];
            Csm[(r+8)*CSM_PITCH + c]   = acc[i][na][2];
            Csm[(r+8)*CSM_PITCH + c+1] = acc[i][na][3];
        }
    }
    __syncthreads();

    float alpha = 1.f / (1.f + expf(-pde_mix[0]));
    const float dtc = 1.f / NSTEPS;
    int wbuf = rbuf ^ 1;

    #pragma unroll
    for (int q = 0; q < 2; q++) {
        int P = q * 256 + tid;          // 0..511
        int m_loc = P >> 2;             // 0..127
        int bg = P & 3;                 // 0..3
        size_t pidx = ((size_t)(brow*128 + m_loc)) * Bb + (bcol*4 + bg);
        float* fb = g_field + pidx * FDm;
        float* sg = g_state + pidx * FDm;
        __half* fh = g_Fh[wbuf] + pidx * FDm;
        const float* crow = Csm + m_loc * CSM_PITCH + bg * 32;

        float x[FDm];
        #pragma unroll
        for (int i = 0; i < 8; i++) *(float4*)&x[i*4] = *(const float4*)(fb + i*4);

        // nf = relu(x@W1+b1)@W2+b2, in two 32-wide halves of the hidden dim
        float nf[FDm];
        #pragma unroll
        for (int f = 0; f < FDm; f++) nf[f] = sbia[64 + f];
        #pragma unroll
        for (int half = 0; half < 2; half++) {
            float h[32];
            #pragma unroll
            for (int hh = 0; hh < 32; hh++) h[hh] = sbia[half*32 + hh];
            #pragma unroll
            for (int k = 0; k < FDm; k++) {
                float xk = x[k];
                #pragma unroll
                for (int hh = 0; hh < 32; hh++)
                    h[hh] = fmaf(xk, sw1[k*HDm + half*32 + hh], h[hh]);
            }
            #pragma unroll
            for (int hh = 0; hh < 32; hh++) {
                float hv = fmaxf(h[hh], 0.f);
                #pragma unroll
                for (int f = 0; f < FDm; f++)
                    nf[f] = fmaf(hv, sw2[(half*32 + hh)*FDm + f], nf[f]);
            }
        }

        // fe = x + (alpha*(AF - x) + (1-alpha)*nf)*dt   (reuse x as fe)
        #pragma unroll
        for (int f = 0; f < FDm; f++) {
            float af = crow[f];
            x[f] = x[f] + (alpha*(af - x[f]) + (1.f - alpha)*nf[f]) * dtc;
        }

        float stv[FDm];
        if (first) {
            #pragma unroll
            for (int f = 0; f < FDm; f++) stv[f] = 0.f;
        } else {
            #pragma unroll
            for (int i = 0; i < 8; i++) *(float4*)&stv[i*4] = *(const float4*)(sg + i*4);
        }

        float sa[FDm];
        #pragma unroll
        for (int f = 0; f < FDm; f++) sa[f] = sbia[96 + f];
        #pragma unroll
        for (int k = 0; k < FDm; k++) {
            float fk = x[k], sk = stv[k];
            #pragma unroll
            for (int f = 0; f < FDm; f++) {
                sa[f] = fmaf(fk, swin[k*FDm + f], sa[f]);
                sa[f] = fmaf(sk, swst[k*FDm + f], sa[f]);
            }
        }
        #pragma unroll
        for (int f = 0; f < FDm; f++) sa[f] = tanhf(sa[f]);
        #pragma unroll
        for (int i = 0; i < 8; i++) *(float4*)(sg + i*4) = *(float4*)&sa[i*4];

        float fo[FDm];
        #pragma unroll
        for (int f = 0; f < FDm; f++) fo[f] = x[f] + sbia[128 + f];
        #pragma unroll
        for (int k = 0; k < FDm; k++) {
            float sk = sa[k];
            #pragma unroll
            for (int f = 0; f < FDm; f++)
                fo[f] = fmaf(sk, swou[k*FDm + f], fo[f]);
        }
        #pragma unroll
        for (int i = 0; i < 8; i++) *(float4*)(fb + i*4) = *(float4*)&fo[i*4];
        #pragma unroll
        for (int f = 0; f < FDm; f += 2) {
            __half2 hv = __floats2half2_rn(fo[f], fo[f+1]);
            *(__half2*)(fh + f) = hv;
        }
    }
}

// ---------------------------------------------------------------------------
// Decoder. One warp per (b,n). out[(b*12+o)*4096 + n]
// ---------------------------------------------------------------------------
__global__ void __launch_bounds__(256) decoder_kernel(
    const float* __restrict__ w1, const float* __restrict__ b1,
    const float* __restrict__ w2, const float* __restrict__ b2,
    float* __restrict__ out)
{
    __shared__ float s_w1[FDm*HDm], s_w2[HDm*OUTD];
    __shared__ float s_b1[HDm], s_b2[OUTD];
    int tid = threadIdx.x;
    for (int i = tid; i < FDm*HDm;  i += 256) s_w1[i] = w1[i];
    for (int i = tid; i < HDm*OUTD; i += 256) s_w2[i] = w2[i];
    if (tid < HDm) s_b1[tid] = b1[tid];
    if (tid < OUTD) s_b2[tid] = b2[tid];
    __syncthreads();

    int warp = (blockIdx.x * 256 + tid) >> 5;
    int lane = tid & 31;
    int b = warp & 63;
    int n = warp >> 6;

    float fld = g_field[(size_t)n * BF + b*FDm + lane];
    float h0 = s_b1[lane], h1 = s_b1[32 + lane];
    #pragma unroll
    for (int k = 0; k < FDm; k++) {
        float fk = __shfl_sync(0xffffffffu, fld, k);
        h0 = fmaf(fk, s_w1[k*HDm + lane],      h0);
        h1 = fmaf(fk, s_w1[k*HDm + 32 + lane], h1);
    }
    h0 = fmaxf(h0, 0.f); h1 = fmaxf(h1, 0.f);

    float o = (lane < OUTD) ? s_b2[lane] : 0.f;
    #pragma unroll
    for (int hh = 0; hh < HDm; hh++) {
        float v = __shfl_sync(0xffffffffu, (hh < 32) ? h0 : h1, hh & 31);
        if (lane < OUTD) o = fmaf(v, s_w2[hh*OUTD + lane], o);
    }
    if (lane < OUTD)
        out[((size_t)b*OUTD + lane)*Nn + n] = o;
}

// ---------------------------------------------------------------------------
extern "C" void kernel_launch(void* const* d_in, const int* in_sizes, int n_in,
                              void* d_out, int out_size)
{
    const float* hist     = (const float*)d_in[0];
    const float* tid_emb  = (const float*)d_in[5];
    const float* diw_emb  = (const float*)d_in[6];
    const float* t2f_w    = (const float*)d_in[7];
    const float* t2f_b    = (const float*)d_in[8];
    const float* enc_w1   = (const float*)d_in[9];
    const float* enc_b1   = (const float*)d_in[10];
    const float* enc_w2   = (const float*)d_in[11];
    const float* enc_b2   = (const float*)d_in[12];
    const float* node_emb = (const float*)d_in[13];
    const float* pde_w1   = (const float*)d_in[14];
    const float* pde_b1   = (const float*)d_in[15];
    const float* pde_w2   = (const float*)d_in[16];
    const float* pde_b2   = (const float*)d_in[17];
    const float* ss_win   = (const float*)d_in[18];
    const float* ss_wst   = (const float*)d_in[19];
    const float* ss_b     = (const float*)d_in[20];
    const float* ss_wout  = (const float*)d_in[21];
    const float* ss_bout  = (const float*)d_in[22];
    const float* dec_w1   = (const float*)d_in[23];
    const float* dec_b1   = (const float*)d_in[24];
    const float* dec_w2   = (const float*)d_in[25];
    const float* dec_b2   = (const float*)d_in[26];
    const float* pde_mix  = (const float*)d_in[27];

    static int smem_set = 0;
    if (!smem_set) {
        cudaFuncSetAttribute(gemm_fused, cudaFuncAttributeMaxDynamicSharedMemorySize, GSMEM);
        smem_set = 1;
    }

    build_A<<<Nn, 256>>>(node_emb);

    encoder_kernel<<<(Bb*Nn)/8, 256>>>(hist, tid_emb, diw_emb, t2f_w, t2f_b,
                                       enc_w1, enc_b1, enc_w2, enc_b2);

    for (int s = 0; s < NSTEPS; s++) {
        gemm_fused<<<dim3(BF/128, Nn/128), 256, GSMEM>>>(
            pde_w1, pde_b1, pde_w2, pde_b2,
            ss_win, ss_wst, ss_b, ss_wout, ss_bout,
            pde_mix, s == 0, s & 1);
    }

    decoder_kernel<<<(Bb*Nn)/8, 256>>>(dec_w1, dec_b1, dec_w2, dec_b2,
                                       (float*)d_out);
}

// round 11
// speedup vs baseline: 1.7344x; 1.0118x over previous
#include <cuda_runtime.h>
#include <cuda_fp16.h>
#include <math.h>
#include <cstdint>

#define Bb 64
#define Ll 12
#define Nn 4096
#define Cc 3
#define FDm 32
#define HDm 64
#define OUTD 12
#define TIDn 288
#define DIWn 7
#define TDm 16
#define NSTEPS 4
#define EMBm 10
#define BF (Bb*FDm)   // 2048

// Scratch (device globals)
__device__ float g_field[(size_t)Nn*BF];                    // field[m][j], j=b*32+f
__device__ float g_state[(size_t)Nn*BF];
__device__ __align__(16) __half g_Ah[(size_t)Nn*Nn];        // A fp16 [n][m]
__device__ __align__(16) __half g_Fh[2][(size_t)Nn*BF];     // field fp16 [m][j], dbl-buf

// ------------------------------ PTX helpers -------------------------------
__device__ __forceinline__ uint32_t smem_to_u32(const void* p) {
    uint32_t a;
    asm("{ .reg .u64 t; cvta.to.shared.u64 t, %1; cvt.u32.u64 %0, t; }"
        : "=r"(a) : "l"(p));
    return a;
}
__device__ __forceinline__ void cp16(uint32_t dst, const void* src) {
    asm volatile("cp.async.cg.shared.global [%0], [%1], 16;" :: "r"(dst), "l"(src));
}
#define CP_COMMIT() asm volatile("cp.async.commit_group;" ::: "memory")
#define CP_WAIT(n)  asm volatile("cp.async.wait_group %0;" :: "n"(n) : "memory")

__device__ __forceinline__ void ldsm4(uint32_t* r, uint32_t addr) {
    asm volatile("ldmatrix.sync.aligned.m8n8.x4.shared.b16 {%0,%1,%2,%3}, [%4];"
                 : "=r"(r[0]), "=r"(r[1]), "=r"(r[2]), "=r"(r[3]) : "r"(addr));
}
__device__ __forceinline__ void ldsm4t(uint32_t* r, uint32_t addr) {
    asm volatile("ldmatrix.sync.aligned.m8n8.x4.trans.shared.b16 {%0,%1,%2,%3}, [%4];"
                 : "=r"(r[0]), "=r"(r[1]), "=r"(r[2]), "=r"(r[3]) : "r"(addr));
}
__device__ __forceinline__ void mma_f16(float* c, const uint32_t* a, const uint32_t* b) {
    asm volatile("mma.sync.aligned.m16n8k16.row.col.f32.f16.f16.f32 "
                 "{%0,%1,%2,%3}, {%4,%5,%6,%7}, {%8,%9}, {%0,%1,%2,%3};"
                 : "+f"(c[0]), "+f"(c[1]), "+f"(c[2]), "+f"(c[3])
                 : "r"(a[0]), "r"(a[1]), "r"(a[2]), "r"(a[3]), "r"(b[0]), "r"(b[1]));
}

// ---------------------------------------------------------------------------
// A = softmax(relu(node_emb @ node_emb^T)); register-resident row, fp16 out.
// emb rows are 40B (8-aligned) -> 5x float2 loads per row.
// ---------------------------------------------------------------------------
__global__ void __launch_bounds__(256) build_A(const float* __restrict__ emb) {
    int n = blockIdx.x;
    int tid = threadIdx.x;
    __shared__ float en[EMBm];
    __shared__ float red[256];
    if (tid < EMBm) en[tid] = emb[n*EMBm + tid];
    __syncthreads();
    float e0 = en[0], e1 = en[1], e2 = en[2], e3 = en[3], e4 = en[4];
    float e5 = en[5], e6 = en[6], e7 = en[7], e8 = en[8], e9 = en[9];

    float r[16];
    float lmax = 0.f;
    #pragma unroll
    for (int j = 0; j < 16; j++) {
        int m = j * 256 + tid;
        const float2* ep = (const float2*)(emb + (size_t)m * EMBm);
        float2 p0 = ep[0], p1 = ep[1], p2 = ep[2], p3 = ep[3], p4 = ep[4];
        float d = e0*p0.x + e1*p0.y + e2*p1.x + e3*p1.y + e4*p2.x
                + e5*p2.y + e6*p3.x + e7*p3.y + e8*p4.x + e9*p4.y;
        d = fmaxf(d, 0.f);
        r[j] = d;
        lmax = fmaxf(lmax, d);
    }
    red[tid] = lmax; __syncthreads();
    for (int s = 128; s > 0; s >>= 1) {
        if (tid < s) red[tid] = fmaxf(red[tid], red[tid+s]);
        __syncthreads();
    }
    float mx = red[0];
    __syncthreads();

    float lsum = 0.f;
    #pragma unroll
    for (int j = 0; j < 16; j++) {
        float e = expf(r[j] - mx);
        r[j] = e;
        lsum += e;
    }
    red[tid] = lsum; __syncthreads();
    for (int s = 128; s > 0; s >>= 1) {
        if (tid < s) red[tid] += red[tid+s];
        __syncthreads();
    }
    float inv = 1.f / red[0];

    #pragma unroll
    for (int j = 0; j < 16; j++) {
        int m = j * 256 + tid;
        g_Ah[(size_t)n*Nn + m] = __float2half_rn(r[j] * inv);
    }
}

// ---------------------------------------------------------------------------
// Encoder + temporal embedding. Warp-per-point with grid-stride (512 blocks,
// each warp handles 64 points) -- weights loaded once per block.
// ---------------------------------------------------------------------------
#define ENC_BLOCKS 512
__global__ void __launch_bounds__(256) encoder_kernel(
    const float* __restrict__ hist,
    const float* __restrict__ tid_emb, const float* __restrict__ diw_emb,
    const float* __restrict__ t2f_w,   const float* __restrict__ t2f_b,
    const float* __restrict__ w1, const float* __restrict__ b1,
    const float* __restrict__ w2, const float* __restrict__ b2)
{
    __shared__ float s_w1[Ll*Cc*HDm];
    __shared__ float s_w2[HDm*FDm];
    __shared__ float s_t2f[2*TDm*FDm];
    __shared__ float s_b1[HDm];
    __shared__ float s_b2[FDm];
    __shared__ float s_t2fb[FDm];
    int tid = threadIdx.x;
    for (int i = tid; i < Ll*Cc*HDm; i += 256) s_w1[i] = w1[i];
    for (int i = tid; i < HDm*FDm;   i += 256) s_w2[i] = w2[i];
    for (int i = tid; i < 2*TDm*FDm; i += 256) s_t2f[i] = t2f_w[i];
    if (tid < HDm) s_b1[tid] = b1[tid];
    if (tid < FDm) { s_b2[tid] = b2[tid]; s_t2fb[tid] = t2f_b[tid]; }
    __syncthreads();

    int lane = tid & 31;
    int gw = (blockIdx.x * 256 + tid) >> 5;   // 0..4095

    for (int it = 0; it < (Bb*Nn)/(ENC_BLOCKS*8); it++) {
        int P = it * (ENC_BLOCKS*8) + gw;
        int n = P & (Nn - 1);
        int b = P >> 12;

        const float* hb = hist + ((size_t)b * Ll * Nn + n) * Cc;
        float x[Ll*Cc];
        #pragma unroll
        for (int l = 0; l < Ll; l++)
            #pragma unroll
            for (int c = 0; c < Cc; c++)
                x[l*Cc + c] = hb[(size_t)l * Nn * Cc + c];

        float h0 = s_b1[lane], h1 = s_b1[32 + lane];
        #pragma unroll
        for (int k = 0; k < Ll*Cc; k++) {
            h0 = fmaf(x[k], s_w1[k*HDm + lane],      h0);
            h1 = fmaf(x[k], s_w1[k*HDm + 32 + lane], h1);
        }
        h0 = fmaxf(h0, 0.f); h1 = fmaxf(h1, 0.f);

        float acc = s_b2[lane];
        #pragma unroll
        for (int hh = 0; hh < HDm; hh++) {
            float v = __shfl_sync(0xffffffffu, (hh < 32) ? h0 : h1, hh & 31);
            acc = fmaf(v, s_w2[hh*FDm + lane], acc);
        }

        float v1 = hb[(size_t)(Ll-1)*Nn*Cc + 1];
        float v2 = hb[(size_t)(Ll-1)*Nn*Cc + 2];
        int ti = (int)(v1 * (float)TIDn); ti = min(max(ti, 0), TIDn-1);
        int di = (int)(v2 * (float)DIWn); di = min(max(di, 0), DIWn-1);
        #pragma unroll
        for (int k = 0; k < TDm; k++)
            acc = fmaf(tid_emb[ti*TDm + k], s_t2f[k*FDm + lane], acc);
        #pragma unroll
        for (int k = 0; k < TDm; k++)
            acc = fmaf(diw_emb[di*TDm + k], s_t2f[(TDm + k)*FDm + lane], acc);
        acc += s_t2fb[lane];

        size_t off = (size_t)n * BF + b*FDm + lane;
        g_field[off] = acc;
        g_Fh[0][off] = __float2half_rn(acc);
    }
}

// ---------------------------------------------------------------------------
// FUSED: fp16 GEMM (AF = A @ field) + step-MLP epilogue; last step also
// runs the decoder and writes pred directly to d_out.
// ---------------------------------------------------------------------------
#define BKg 32
#define LDAe 40
#define TA_BYTES (128*LDAe*2)          // 10240
#define LDBB 136
#define TB_BYTES (BKg*LDBB*2)          // 8704
#define STG_BYTES (TA_BYTES + TB_BYTES)  // 18944
#define NST 4
#define CSM_PITCH 132
#define CSM_BYTES (128*CSM_PITCH*4)    // 67584
#define WGT_FLOATS (2048+2048+3*1024+160+2048+64+768+12)   // 10220
#define GSMEM (CSM_BYTES + WGT_FLOATS*4)                   // 108464

__global__ void __launch_bounds__(256, 2) gemm_fused(
    const float* __restrict__ pw1, const float* __restrict__ pb1,
    const float* __restrict__ pw2, const float* __restrict__ pb2,
    const float* __restrict__ win, const float* __restrict__ wst,
    const float* __restrict__ sb,  const float* __restrict__ wout,
    const float* __restrict__ bout, const float* __restrict__ pde_mix,
    const float* __restrict__ dw1, const float* __restrict__ db1,
    const float* __restrict__ dw2, const float* __restrict__ db2,
    float* __restrict__ out,
    int first, int last, int rbuf)
{
    extern __shared__ char smem[];
    uint32_t sbase = smem_to_u32(smem);
    int tid = threadIdx.x;
    int lane = tid & 31;
    int wid = tid >> 5;
    int bcol = blockIdx.x;    // 0..15
    int brow = blockIdx.y;    // 0..31

    const __half* Ah = g_Ah + (size_t)brow * 128 * Nn;
    const __half* Bg = g_Fh[rbuf] + (size_t)bcol * 128;

    int alr = tid >> 1;
    int alc = (tid & 1) * 16;
    size_t gA = (size_t)alr * Nn + alc;
    uint32_t sA = sbase + alr * (LDAe*2) + alc * 2;
    int blr = tid >> 3;
    int blc = (tid & 7) * 16;
    uint32_t sB = sbase + TA_BYTES + blr * (LDBB*2) + blc * 2;

    int warp_m = wid & 1;
    int warp_n = wid >> 1;
    int m_base = warp_m * 64;
    int n_base = warp_n * 32;

    float acc[4][4][4];
    #pragma unroll
    for (int i = 0; i < 4; i++)
        #pragma unroll
        for (int j = 0; j < 4; j++)
            #pragma unroll
            for (int q = 0; q < 4; q++) acc[i][j][q] = 0.f;

    uint32_t a_off[4];
    #pragma unroll
    for (int i = 0; i < 4; i++)
        a_off[i] = (m_base + i*16 + (lane & 15)) * (LDAe*2) + ((lane >> 4) * 8) * 2;
    uint32_t b_off[2];
    {
        int i = lane >> 3;
        #pragma unroll
        for (int nj = 0; nj < 2; nj++)
            b_off[nj] = ((i & 1) * 8 + (lane & 7)) * (LDBB*2)
                      + (n_base + nj*16 + (i >> 1) * 8) * 2;
    }

    const int NIT = Nn / BKg;   // 128

    #pragma unroll
    for (int p = 0; p < 3; p++) {
        uint32_t d = p * STG_BYTES;
        size_t kg = (size_t)p * BKg;
        cp16(sA + d,      Ah + gA + kg); cp16(sA + d + 16, Ah + gA + kg + 8);
        const __half* bs = Bg + (kg + blr) * BF + blc;
        cp16(sB + d,      bs);           cp16(sB + d + 16, bs + 8);
        CP_COMMIT();
    }

    for (int it = 0; it < NIT; it++) {
        CP_WAIT(2);
        __syncthreads();

        if (it + 3 < NIT) {
            uint32_t d = ((it + 3) & 3) * STG_BYTES;
            size_t kg = (size_t)(it + 3) * BKg;
            cp16(sA + d,      Ah + gA + kg); cp16(sA + d + 16, Ah + gA + kg + 8);
            const __half* bs = Bg + (kg + blr) * BF + blc;
            cp16(sB + d,      bs);           cp16(sB + d + 16, bs + 8);
        }
        CP_COMMIT();

        uint32_t st = sbase + (it & 3) * STG_BYTES;
        #pragma unroll
        for (int kk = 0; kk < 2; kk++) {
            uint32_t af[4][4];
            #pragma unroll
            for (int i = 0; i < 4; i++)
                ldsm4(af[i], st + a_off[i] + kk * 32);
            uint32_t bf[2][4];
            #pragma unroll
            for (int j = 0; j < 2; j++)
                ldsm4t(bf[j], st + TA_BYTES + b_off[j] + kk * 16 * (LDBB*2));
            #pragma unroll
            for (int i = 0; i < 4; i++)
                #pragma unroll
                for (int na = 0; na < 4; na++)
                    mma_f16(acc[i][na], af[i], &bf[na >> 1][(na & 1) * 2]);
        }
    }
    CP_WAIT(0);
    __syncthreads();

    // ---------------- epilogue ----------------
    float* Csm  = (float*)smem;                 // [128][132]
    float* sw1  = (float*)(smem + CSM_BYTES);
    float* sw2  = sw1 + 2048;
    float* swin = sw2 + 2048;
    float* swst = swin + 1024;
    float* swou = swst + 1024;
    float* sbia = swou + 1024;                  // b1[64] b2[32] sb[32] bout[32]
    float* sdw1 = sbia + 160;                   // 32x64
    float* sdb1 = sdw1 + 2048;                  // 64
    float* sdw2 = sdb1 + 64;                    // 64x12
    float* sdb2 = sdw2 + 768;                   // 12

    for (int i = tid; i < 2048; i += 256) { sw1[i] = pw1[i]; sw2[i] = pw2[i]; }
    for (int i = tid; i < 1024; i += 256) { swin[i] = win[i]; swst[i] = wst[i]; swou[i] = wout[i]; }
    if (tid < 64) sbia[tid] = pb1[tid];
    if (tid < 32) { sbia[64+tid] = pb2[tid]; sbia[96+tid] = sb[tid]; sbia[128+tid] = bout[tid]; }
    if (last) {
        for (int i = tid; i < 2048; i += 256) sdw1[i] = dw1[i];
        for (int i = tid; i < 768;  i += 256) sdw2[i] = dw2[i];
        if (tid < 64) sdb1[tid] = db1[tid];
        if (tid < OUTD) sdb2[tid] = db2[tid];
    }

    #pragma unroll
    for (int i = 0; i < 4; i++) {
        int r = m_base + i*16 + (lane >> 2);
        #pragma unroll
        for (int na = 0; na < 4; na++) {
            int c = n_base + na*8 + 2*(lane & 3);
            Csm[r*CSM_PITCH + c]       = acc[i][na][0];
            Csm[r*CSM_PITCH + c + 1]   = acc[i][na][1];
            Csm[(r+8)*CSM_PITCH + c]   = acc[i][na][2];
            Csm[(r+8)*CSM_PITCH + c+1] = acc[i][na][3];
        }
    }
    __syncthreads();

    float alpha = 1.f / (1.f + expf(-pde_mix[0]));
    const float dtc = 1.f / NSTEPS;
    int wbuf = rbuf ^ 1;

    #pragma unroll
    for (int q = 0; q < 2; q++) {
        int P = q * 256 + tid;
        int m_loc = P >> 2;
        int bg = P & 3;
        int n_glob = brow*128 + m_loc;
        int b_glob = bcol*4 + bg;
        size_t pidx = (size_t)n_glob * Bb + b_glob;
        float* fb = g_field + pidx * FDm;
        float* sg = g_state + pidx * FDm;
        __half* fh = g_Fh[wbuf] + pidx * FDm;
        const float* crow = Csm + m_loc * CSM_PITCH + bg * 32;

        float x[FDm];
        #pragma unroll
        for (int i = 0; i < 8; i++) *(float4*)&x[i*4] = *(const float4*)(fb + i*4);

        float nf[FDm];
        #pragma unroll
        for (int f = 0; f < FDm; f++) nf[f] = sbia[64 + f];
        #pragma unroll
        for (int half = 0; half < 2; half++) {
            float h[32];
            #pragma unroll
            for (int hh = 0; hh < 32; hh++) h[hh] = sbia[half*32 + hh];
            #pragma unroll
            for (int k = 0; k < FDm; k++) {
                float xk = x[k];
                #pragma unroll
                for (int hh = 0; hh < 32; hh++)
                    h[hh] = fmaf(xk, sw1[k*HDm + half*32 + hh], h[hh]);
            }
            #pragma unroll
            for (int hh = 0; hh < 32; hh++) {
                float hv = fmaxf(h[hh], 0.f);
                #pragma unroll
                for (int f = 0; f < FDm; f++)
                    nf[f] = fmaf(hv, sw2[(half*32 + hh)*FDm + f], nf[f]);
            }
        }

        #pragma unroll
        for (int f = 0; f < FDm; f++) {
            float af = crow[f];
            x[f] = x[f] + (alpha*(af - x[f]) + (1.f - alpha)*nf[f]) * dtc;
        }

        float stv[FDm];
        if (first) {
            #pragma unroll
            for (int f = 0; f < FDm; f++) stv[f] = 0.f;
        } else {
            #pragma unroll
            for (int i = 0; i < 8; i++) *(float4*)&stv[i*4] = *(const float4*)(sg + i*4);
        }

        float sa[FDm];
        #pragma unroll
        for (int f = 0; f < FDm; f++) sa[f] = sbia[96 + f];
        #pragma unroll
        for (int k = 0; k < FDm; k++) {
            float fk = x[k], sk = stv[k];
            #pragma unroll
            for (int f = 0; f < FDm; f++) {
                sa[f] = fmaf(fk, swin[k*FDm + f], sa[f]);
                sa[f] = fmaf(sk, swst[k*FDm + f], sa[f]);
            }
        }
        #pragma unroll
        for (int f = 0; f < FDm; f++) sa[f] = tanhf(sa[f]);

        float fo[FDm];
        #pragma unroll
        for (int f = 0; f < FDm; f++) fo[f] = x[f] + sbia[128 + f];
        #pragma unroll
        for (int k = 0; k < FDm; k++) {
            float sk = sa[k];
            #pragma unroll
            for (int f = 0; f < FDm; f++)
                fo[f] = fmaf(sk, swou[k*FDm + f], fo[f]);
        }

        if (!last) {
            #pragma unroll
            for (int i = 0; i < 8; i++) *(float4*)(sg + i*4) = *(float4*)&sa[i*4];
            #pragma unroll
            for (int i = 0; i < 8; i++) *(float4*)(fb + i*4) = *(float4*)&fo[i*4];
            #pragma unroll
            for (int f = 0; f < FDm; f += 2)
                *(__half2*)(fh + f) = __floats2half2_rn(fo[f], fo[f+1]);
        } else {
            // decoder: pred = relu(fo @ dw1 + db1) @ dw2 + db2
            float pred[OUTD];
            #pragma unroll
            for (int o = 0; o < OUTD; o++) pred[o] = sdb2[o];
            #pragma unroll
            for (int half = 0; half < 2; half++) {
                float hd[32];
                #pragma unroll
                for (int hh = 0; hh < 32; hh++) hd[hh] = sdb1[half*32 + hh];
                #pragma unroll
                for (int k = 0; k < FDm; k++) {
                    float fk = fo[k];
                    #pragma unroll
                    for (int hh = 0; hh < 32; hh++)
                        hd[hh] = fmaf(fk, sdw1[k*HDm + half*32 + hh], hd[hh]);
                }
                #pragma unroll
                for (int hh = 0; hh < 32; hh++) {
                    float hv = fmaxf(hd[hh], 0.f);
                    #pragma unroll
                    for (int o = 0; o < OUTD; o++)
                        pred[o] = fmaf(hv, sdw2[(half*32 + hh)*OUTD + o], pred[o]);
                }
            }
            #pragma unroll
            for (int o = 0; o < OUTD; o++)
                out[((size_t)b_glob*OUTD + o)*Nn + n_glob] = pred[o];
        }
    }
}

// ---------------------------------------------------------------------------
extern "C" void kernel_launch(void* const* d_in, const int* in_sizes, int n_in,
                              void* d_out, int out_size)
{
    const float* hist     = (const float*)d_in[0];
    const float* tid_emb  = (const float*)d_in[5];
    const float* diw_emb  = (const float*)d_in[6];
    const float* t2f_w    = (const float*)d_in[7];
    const float* t2f_b    = (const float*)d_in[8];
    const float* enc_w1   = (const float*)d_in[9];
    const float* enc_b1   = (const float*)d_in[10];
    const float* enc_w2   = (const float*)d_in[11];
    const float* enc_b2   = (const float*)d_in[12];
    const float* node_emb = (const float*)d_in[13];
    const float* pde_w1   = (const float*)d_in[14];
    const float* pde_b1   = (const float*)d_in[15];
    const float* pde_w2   = (const float*)d_in[16];
    const float* pde_b2   = (const float*)d_in[17];
    const float* ss_win   = (const float*)d_in[18];
    const float* ss_wst   = (const float*)d_in[19];
    const float* ss_b     = (const float*)d_in[20];
    const float* ss_wout  = (const float*)d_in[21];
    const float* ss_bout  = (const float*)d_in[22];
    const float* dec_w1   = (const float*)d_in[23];
    const float* dec_b1   = (const float*)d_in[24];
    const float* dec_w2   = (const float*)d_in[25];
    const float* dec_b2   = (const float*)d_in[26];
    const float* pde_mix  = (const float*)d_in[27];

    static int smem_set = 0;
    if (!smem_set) {
        cudaFuncSetAttribute(gemm_fused, cudaFuncAttributeMaxDynamicSharedMemorySize, GSMEM);
        smem_set = 1;
    }

    build_A<<<Nn, 256>>>(node_emb);

    encoder_kernel<<<ENC_BLOCKS, 256>>>(hist, tid_emb, diw_emb, t2f_w, t2f_b,
                                        enc_w1, enc_b1, enc_w2, enc_b2);

    for (int s = 0; s < NSTEPS; s++) {
        gemm_fused<<<dim3(BF/128, Nn/128), 256, GSMEM>>>(
            pde_w1, pde_b1, pde_w2, pde_b2,
            ss_win, ss_wst, ss_b, ss_wout, ss_bout, pde_mix,
            dec_w1, dec_b1, dec_w2, dec_b2, (float*)d_out,
            s == 0, s == NSTEPS-1, s & 1);
    }
}